// round 4
// baseline (speedup 1.0000x reference)
#include <cuda_runtime.h>
#include <cuda_bf16.h>

// Retrace: per-(b,d) reverse affine scan + MSE reduction.
// Shapes: B=2048, T=512, D=16. fp32. Output: 1 fp32 scalar.
// Segment-parallel affine scan (q = P*x + S per 64-step segment; MSE quadratic
// in carry-in x). This round: float2 loads (lane = 2 adjacent d), __ldcs
// streaming on the 5 read-once arrays, warp = 4 b-rows x 8 d-pairs.

#define RB 2048
#define RT 512
#define RD 16
#define NSEG 8
#define SEGLEN 64
#define CHAINS_PER_BLK 64     // 32 lanes x 2 chains
#define GAMMA 0.99f

__global__ __launch_bounds__(256, 3)
void retrace_seg2_kernel(const float* __restrict__ Q,
                         const float* __restrict__ eQ,
                         const float* __restrict__ tQ,
                         const float* __restrict__ rw,
                         const float* __restrict__ tpp,
                         const float* __restrict__ bpp,
                         float* __restrict__ out)
{
    const int lane = threadIdx.x & 31;
    const int seg  = threadIdx.x >> 5;          // time segment 0..7
    // lane -> (b within block-group, d-pair)
    const int b_off = lane >> 3;                // 0..3
    const int d2    = (lane & 7) * 2;           // 0,2,..,14
    const int b = blockIdx.x * 4 + b_off;

    const size_t base = (size_t)b * (RT * RD) + d2;     // float index
    const float2* q_p   = (const float2*)(Q   + base);
    const float2* e_p   = (const float2*)(eQ  + base);
    const float2* tq_p  = (const float2*)(tQ  + base);
    const float2* r_p   = (const float2*)(rw  + base);
    const float2* tpp_p = (const float2*)(tpp + base);
    const float*  bpp_p = bpp + (size_t)b * RT;
    const int RD2 = RD / 2;                      // float2 stride per t

    const int lo = seg * SEGLEN;
    const int hi = (seg == NSEG - 1) ? (RT - 2) : (lo + SEGLEN - 1);

    // two independent chains per lane
    float P0 = 1.0f, S0 = 0.0f, D20 = 0.0f, DP0 = 0.0f, P20 = 0.0f;
    float P1 = 1.0f, S1 = 0.0f, D21 = 0.0f, DP1 = 0.0f, P21 = 0.0f;

    #pragma unroll 4
    for (int t = hi; t >= lo; --t) {
        const int j = t + 1;
        float  lb = __ldg(bpp_p + j);
        float2 lt = __ldcs(tpp_p + j * RD2);
        float2 le = __ldcs(e_p   + j * RD2);
        float2 lq = __ldcs(tq_p  + j * RD2);
        float2 lr = __ldcs(r_p   + t * RD2);
        float2 lQ = __ldcs(q_p   + t * RD2);

        float gc0 = GAMMA * __expf(fminf(lt.x - lb, 0.0f));
        float gc1 = GAMMA * __expf(fminf(lt.y - lb, 0.0f));

        float bse0 = fmaf(GAMMA, le.x, lr.x); bse0 = fmaf(-gc0, lq.x, bse0);
        float bse1 = fmaf(GAMMA, le.y, lr.y); bse1 = fmaf(-gc1, lq.y, bse1);

        P0 = gc0 * P0;  S0 = fmaf(gc0, S0, bse0);
        P1 = gc1 * P1;  S1 = fmaf(gc1, S1, bse1);

        float dv0 = lQ.x - S0;
        float dv1 = lQ.y - S1;
        D20 = fmaf(dv0, dv0, D20);  DP0 = fmaf(dv0, P0, DP0);  P20 = fmaf(P0, P0, P20);
        D21 = fmaf(dv1, dv1, D21);  DP1 = fmaf(dv1, P1, DP1);  P21 = fmaf(P1, P1, P21);
    }

    // shared: [NSEG][64 chains] for 5 quantities
    __shared__ float shA [NSEG][CHAINS_PER_BLK];
    __shared__ float shB [NSEG][CHAINS_PER_BLK];
    __shared__ float shD2[NSEG][CHAINS_PER_BLK];
    __shared__ float shDP[NSEG][CHAINS_PER_BLK];
    __shared__ float shP2[NSEG][CHAINS_PER_BLK];
    const int c0 = lane * 2, c1 = c0 + 1;
    shA [seg][c0] = P0;  shA [seg][c1] = P1;
    shB [seg][c0] = S0;  shB [seg][c1] = S1;
    shD2[seg][c0] = D20; shD2[seg][c1] = D21;
    shDP[seg][c0] = DP0; shDP[seg][c1] = DP1;
    shP2[seg][c0] = P20; shP2[seg][c1] = P21;
    __syncthreads();

    // warp 0 combines: each lane handles its own 2 chains (same c0/c1 mapping)
    if (seg == 0) {
        float2 x2 = __ldg(tq_p + (RT - 1) * RD2);  // carry init = target_Q[:, -1]
        float acc = 0.0f;
        float x0 = x2.x, x1 = x2.y;
        #pragma unroll
        for (int s = NSEG - 1; s >= 0; --s) {
            acc += fmaf(x0, fmaf(x0, shP2[s][c0], -2.0f * shDP[s][c0]), shD2[s][c0]);
            acc += fmaf(x1, fmaf(x1, shP2[s][c1], -2.0f * shDP[s][c1]), shD2[s][c1]);
            x0 = fmaf(shA[s][c0], x0, shB[s][c0]);
            x1 = fmaf(shA[s][c1], x1, shB[s][c1]);
        }
        const float inv_n = 1.0f / (float)((size_t)RB * (RT - 1) * RD);
        acc *= inv_n;

        #pragma unroll
        for (int off = 16; off > 0; off >>= 1)
            acc += __shfl_down_sync(0xFFFFFFFFu, acc, off);
        if (lane == 0)
            atomicAdd(out, acc);
    }
}

extern "C" void kernel_launch(void* const* d_in, const int* in_sizes, int n_in,
                              void* d_out, int out_size)
{
    const float* Q   = (const float*)d_in[0];
    const float* eQ  = (const float*)d_in[1];
    const float* tQ  = (const float*)d_in[2];
    const float* rw  = (const float*)d_in[3];
    const float* tpp = (const float*)d_in[4];
    const float* bpp = (const float*)d_in[5];
    float* out = (float*)d_out;

    cudaMemsetAsync(out, 0, sizeof(float), 0);

    const int blocks = (RB * RD) / CHAINS_PER_BLK;   // 512
    retrace_seg2_kernel<<<blocks, NSEG * 32>>>(Q, eQ, tQ, rw, tpp, bpp, out);
}